// round 16
// baseline (speedup 1.0000x reference)
#include <cuda_runtime.h>
#include <cuda_fp16.h>
#include <math.h>
#include <stdint.h>

#define BB 8
#define CIN 96
#define CC 192
#define HH 128
#define WW 128
#define HEADS 8
#define HD 24
#define TT 131072
#define FF 768
#define KCONV 864   // 9*96

// pipeline: K-tile = 32 halves (64B/row), block tile 128x64, 3 CTAs/SM
#define ST 5
#define AWORDS (128*16)
#define BWORDS (64*16)
#define SMEMB (ST*(AWORDS+BWORDS)*4)
#define FLSMEM (64*193*4)

// attention smem (halves offsets)
#define AT_Q  0
#define AT_K  16384
#define AT_V  32768
#define AT_VS 49152
#define AT_RPB_B 123904
#define AT_SMEM (123904 + 7200)

// ---------------- scratch ----------------
__device__ __half g_nx[BB*CIN*HH*WW];
__device__ __half g_nv[BB*CIN*HH*WW];
__device__ __half g_xp[TT*CC];
__device__ __half g_vp[TT*CC];
__device__ __half g_xs[TT*CC];
__device__ __half g_vs[TT*CC];
__device__ __half g_q [(long)TT*256];    // [t][8 heads][32 padded hperm]
__device__ __half g_kv[(long)TT*512];    // [t][K: 8x32 padded hperm][V: 192 natural][64 pad]
__device__ __half g_at[TT*CC];
__device__ __half g_pr[TT*CC];
__device__ __half g_l3[TT*CC];
__device__ __half g_h1[(long)TT*FF];
__device__ __half g_m [TT*CC];
// weights: n-major, k-contiguous, k hperm'd, fp16
__device__ __half g_qwP [CC*CC];
__device__ __half g_kvwP[2*CC*CC];
__device__ __half g_apwP[CC*CC];
__device__ __half g_f1wP[FF*CC];
__device__ __half g_f2wP[CC*FF];
__device__ __half g_cqwP[CC*KCONV];
__device__ __half g_cvwP[CC*KCONV];

// ---------------- helpers ----------------
__device__ __forceinline__ int hperm(int k) {
    int r = k & 15;
    return (k & ~15) | (((r & 7) >> 1) << 2) | (((r >> 3) & 1) << 1) | (r & 1);
}
__device__ __forceinline__ __half h16(float x) { return __float2half_rn(x); }
__device__ __forceinline__ uint32_t h2u(float a, float b) {
    __half2 h = __floats2half2_rn(a, b);
    return *reinterpret_cast<uint32_t*>(&h);
}

__device__ __forceinline__ void mma_f16(float* d, const uint32_t* a, const uint32_t* b) {
    asm("mma.sync.aligned.m16n8k16.row.col.f32.f16.f16.f32 "
        "{%0,%1,%2,%3},{%4,%5,%6,%7},{%8,%9},{%10,%11,%12,%13};"
        : "=f"(d[0]), "=f"(d[1]), "=f"(d[2]), "=f"(d[3])
        : "r"(a[0]), "r"(a[1]), "r"(a[2]), "r"(a[3]),
          "r"(b[0]), "r"(b[1]),
          "f"(d[0]), "f"(d[1]), "f"(d[2]), "f"(d[3]));
}
__device__ __forceinline__ void cp16(uint32_t d, const void* s) {
    asm volatile("cp.async.cg.shared.global [%0], [%1], 16;" :: "r"(d), "l"(s));
}
__device__ __forceinline__ void cp16p(uint32_t d, const void* s, int sz) {
    asm volatile("cp.async.cg.shared.global [%0], [%1], 16, %2;" :: "r"(d), "l"(s), "r"(sz));
}
#define CP_COMMIT() asm volatile("cp.async.commit_group;")
#define CP_WAITN()  asm volatile("cp.async.wait_group 3;")

// ---------------- fused weight prep (fp16, hperm) ----------------
#define S1 (CC*CC)
#define S2 (2*CC*CC)
#define S4 (FF*CC)
#define S6 (KCONV*CC)
__global__ void prep_weights(
    const float* __restrict__ qw, const float* __restrict__ kvw, const float* __restrict__ apw,
    const float* __restrict__ f1w, const float* __restrict__ f2w,
    const float* __restrict__ cqw, const float* __restrict__ cvw,
    __half* __restrict__ qwP, __half* __restrict__ kvwP, __half* __restrict__ apwP,
    __half* __restrict__ f1wP, __half* __restrict__ f2wP,
    __half* __restrict__ cqwP, __half* __restrict__ cvwP)
{
    long i = (long)blockIdx.x * 256 + threadIdx.x;
    long o = i;
    if (o < S1) { int n=o/CC, k=o%CC; qwP[(long)n*CC + hperm(k)] = h16(qw[o]); return; }
    o -= S1;
    if (o < S2) { int n=o/CC, k=o%CC; kvwP[(long)n*CC + hperm(k)] = h16(kvw[o]); return; }
    o -= S2;
    if (o < S1) { int n=o/CC, k=o%CC; apwP[(long)n*CC + hperm(k)] = h16(apw[o]); return; }
    o -= S1;
    if (o < S4) { int n=o/CC, k=o%CC; f1wP[(long)n*CC + hperm(k)] = h16(f1w[o]); return; }
    o -= S4;
    if (o < S4) { int n=o/FF, k=o%FF; f2wP[(long)n*FF + hperm(k)] = h16(f2w[o]); return; }
    o -= S4;
    if (o < S6) { int oc=o/(CIN*9), rem=o%(CIN*9); int c=rem/9, kk=rem%9;
                  cqwP[(long)oc*KCONV + hperm(kk*CIN + c)] = h16(cqw[o]); return; }
    o -= S6;
    if (o < S6) { int oc=o/(CIN*9), rem=o%(CIN*9); int c=rem/9, kk=rem%9;
                  cvwP[(long)oc*KCONV + hperm(kk*CIN + c)] = h16(cvw[o]); return; }
}

// ---------------- NCHW -> NHWC (fp16, hperm), x & v in one launch ----------------
__global__ __launch_bounds__(256) void to_nhwc2(
    const float* __restrict__ inx, const float* __restrict__ inv,
    __half* __restrict__ outx, __half* __restrict__ outv)
{
    __shared__ float tile[32][33];
    int bz = blockIdx.z;
    bool sec = bz >= 1024;
    int by = sec ? bz - 1024 : bz;
    const float* in = sec ? inv : inx;
    __half* out = sec ? outv : outx;
    int b = by >> 7, y = by & 127;
    int c0 = blockIdx.y * 32, x0 = blockIdx.x * 32;
    int tx = threadIdx.x, ty = threadIdx.y;
    #pragma unroll
    for (int i = ty; i < 32; i += 8)
        tile[i][tx] = in[((long)(b * CIN + c0 + i) * HH + y) * WW + x0 + tx];
    __syncthreads();
    #pragma unroll
    for (int i = ty; i < 32; i += 8)
        out[((long)(b * HH + y) * WW + x0 + i) * CIN + hperm(c0 + tx)] = h16(tile[tx][i]);
}

// ================= fp16 MMA GEMM: block 128x64, warp 32x32, KT=32, 5 stages ======
// OUT: 1 = half hperm, 2 = half natural
template<bool BIAS, bool GELU, int OUT>
__global__ __launch_bounds__(256, 3) void mm_f16k(
    const __half* __restrict__ A, const __half* __restrict__ W,
    const float* __restrict__ bias, void* __restrict__ Cv,
    int M, int N, int K, float alpha)
{
    extern __shared__ float sm_[];
    float* As = sm_;
    float* Bs = sm_ + ST * AWORDS;
    int tid = threadIdx.x;
    long bm = (long)blockIdx.y * 128;
    int bn = blockIdx.x * 64;
    int wid = tid >> 5, lane = tid & 31;
    int wm = wid >> 1, wn = wid & 1;
    int m0 = wm * 32, n0 = wn * 32;
    int g = lane >> 2, tg = lane & 3;

    int ar = tid >> 2, aseg = tid & 3;
    int asw = aseg ^ (ar & 3);

    uint32_t sAa = (uint32_t)__cvta_generic_to_shared(As);
    uint32_t sBa = (uint32_t)__cvta_generic_to_shared(Bs);
    uint32_t dA = sAa + (ar * 16 + asw * 4) * 4;
    uint32_t dB = sBa + (ar * 16 + asw * 4) * 4;
    const __half* pA = A + (bm + ar) * K + aseg * 8;
    const __half* pB = W + (long)(bn + ar) * K + aseg * 8;
    const uint32_t stA = AWORDS * 4, stB = BWORDS * 4;
    const uint32_t rA = 64 * 16 * 4;
    const long     gA = (long)64 * K;

    int fo0 = (((tg >> 1) ^ (g & 3)) << 2) + ((tg & 1) << 1);
    int fo1 = fo0 ^ 8;

    float acc[2][4][4];
    #pragma unroll
    for (int i = 0; i < 2; i++)
        #pragma unroll
        for (int j = 0; j < 4; j++)
            #pragma unroll
            for (int r = 0; r < 4; r++) acc[i][j][r] = 0.f;

    int NT = K / 32;
    #pragma unroll
    for (int s = 0; s < ST - 1; s++) {
        if (s < NT) {
            cp16(dA + s * stA,      pA + s * 32);
            cp16(dA + s * stA + rA, pA + s * 32 + gA);
            cp16(dB + s * stB,      pB + s * 32);
        }
        CP_COMMIT();
    }
    for (int t = 0; t < NT; t++) {
        int buf = t % ST;
        CP_WAITN();
        __syncthreads();
        int tp = t + ST - 1;
        if (tp < NT) {
            int sb = tp % ST;
            cp16(dA + sb * stA,      pA + tp * 32);
            cp16(dA + sb * stA + rA, pA + tp * 32 + gA);
            cp16(dB + sb * stB,      pB + tp * 32);
        }
        CP_COMMIT();
        const float* as = As + buf * AWORDS;
        const float* bs = Bs + buf * BWORDS;
        #pragma unroll
        for (int s = 0; s < 2; s++) {
            int fo = s ? fo1 : fo0;
            uint32_t af[2][4];
            #pragma unroll
            for (int i = 0; i < 2; i++) {
                uint2 aLo = *(const uint2*)&as[(m0 + i*16 + g)     * 16 + fo];
                uint2 aHi = *(const uint2*)&as[(m0 + i*16 + g + 8) * 16 + fo];
                af[i][0] = aLo.x; af[i][1] = aHi.x; af[i][2] = aLo.y; af[i][3] = aHi.y;
            }
            #pragma unroll
            for (int j = 0; j < 4; j++) {
                uint2 bv = *(const uint2*)&bs[(n0 + j*8 + g) * 16 + fo];
                uint32_t bf[2] = { bv.x, bv.y };
                mma_f16(acc[0][j], af[0], bf);
                mma_f16(acc[1][j], af[1], bf);
            }
        }
    }
    __half* Ch = (__half*)Cv;
    #pragma unroll
    for (int i = 0; i < 2; i++) {
        long row0 = bm + m0 + i * 16 + g;
        #pragma unroll
        for (int j = 0; j < 4; j++) {
            int col = bn + n0 + j * 8 + 2 * tg;
            float b0 = 0.f, b1 = 0.f;
            if (BIAS) { b0 = bias[col]; b1 = bias[col + 1]; }
            #pragma unroll
            for (int half_ = 0; half_ < 2; half_++) {
                long row = row0 + half_ * 8;
                float v0 = (acc[i][j][half_ * 2 + 0] + b0) * alpha;
                float v1 = (acc[i][j][half_ * 2 + 1] + b1) * alpha;
                if (GELU) {
                    v0 = 0.5f * v0 * (1.f + erff(v0 * 0.70710678118654752f));
                    v1 = 0.5f * v1 * (1.f + erff(v1 * 0.70710678118654752f));
                }
                if (OUT == 1) {
                    Ch[row * N + hperm(col)]     = h16(v0);
                    Ch[row * N + hperm(col + 1)] = h16(v1);
                } else {
                    *(__half2*)&Ch[row * N + col] = __floats2half2_rn(v0, v1);
                }
            }
        }
    }
}

// ================= q + kv projections (grid.x = 9), padded half output ==========
__global__ __launch_bounds__(256, 3) void mm_qkv(
    const __half* __restrict__ xs, const __half* __restrict__ vs,
    const __half* __restrict__ qwP, const __half* __restrict__ kvwP,
    __half* __restrict__ qo, __half* __restrict__ kvo, float scaleq)
{
    extern __shared__ float sm_[];
    float* As = sm_;
    float* Bs = sm_ + ST * AWORDS;
    const int K = CC;
    int bx = blockIdx.x;
    bool isq = bx < 3;
    const __half* A = isq ? xs : vs;
    const __half* W = isq ? qwP : kvwP;
    int bn = (isq ? bx : bx - 3) * 64;
    float alpha = isq ? scaleq : 1.f;

    int tid = threadIdx.x;
    long bm = (long)blockIdx.y * 128;
    int wid = tid >> 5, lane = tid & 31;
    int wm = wid >> 1, wn = wid & 1;
    int m0 = wm * 32, n0 = wn * 32;
    int g = lane >> 2, tg = lane & 3;

    int ar = tid >> 2, aseg = tid & 3;
    int asw = aseg ^ (ar & 3);

    uint32_t sAa = (uint32_t)__cvta_generic_to_shared(As);
    uint32_t sBa = (uint32_t)__cvta_generic_to_shared(Bs);
    uint32_t dA = sAa + (ar * 16 + asw * 4) * 4;
    uint32_t dB = sBa + (ar * 16 + asw * 4) * 4;
    const __half* pA = A + (bm + ar) * K + aseg * 8;
    const __half* pB = W + (long)(bn + ar) * K + aseg * 8;
    const uint32_t stA = AWORDS * 4, stB = BWORDS * 4;
    const uint32_t rA = 64 * 16 * 4;
    const long     gA = (long)64 * K;

    int fo0 = (((tg >> 1) ^ (g & 3)) << 2) + ((tg & 1) << 1);
    int fo1 = fo0 ^ 8;

    float acc[2][4][4];
    #pragma unroll
    for (int i = 0; i < 2; i++)
        #pragma unroll
        for (int j = 0; j < 4; j++)
            #pragma unroll
            for (int r = 0; r < 4; r++) acc[i][j][r] = 0.f;

    const int NT = K / 32;   // 6
    #pragma unroll
    for (int s = 0; s < ST - 1; s++) {
        cp16(dA + s * stA,      pA + s * 32);
        cp16(dA + s * stA + rA, pA + s * 32 + gA);
        cp16(dB + s * stB,      pB + s * 32);
        CP_COMMIT();
    }
    for (int t = 0; t < NT; t++) {
        int buf = t % ST;
        CP_WAITN();
        __syncthreads();
        int tp = t + ST - 1;
        if (tp < NT) {
            int sb = tp % ST;
            cp16(dA + sb * stA,      pA + tp * 32);
            cp16(dA + sb * stA + rA, pA + tp * 32 + gA);
            cp16(dB + sb * stB,      pB + tp * 32);
        }
        CP_COMMIT();
        const float* as = As + buf * AWORDS;
        const float* bs = Bs + buf * BWORDS;
        #pragma unroll
        for (int s = 0; s < 2; s++) {
            int fo = s ? fo1 : fo0;
            uint32_t af[2][4];
            #pragma unroll
            for (int i = 0; i < 2; i++) {
                uint2 aLo = *(const uint2*)&as[(m0 + i*16 + g)     * 16 + fo];
                uint2 aHi = *(const uint2*)&as[(m0 + i*16 + g + 8) * 16 + fo];
                af[i][0] = aLo.x; af[i][1] = aHi.x; af[i][2] = aLo.y; af[i][3] = aHi.y;
            }
            #pragma unroll
            for (int j = 0; j < 4; j++) {
                uint2 bv = *(const uint2*)&bs[(n0 + j*8 + g) * 16 + fo];
                uint32_t bf[2] = { bv.x, bv.y };
                mma_f16(acc[0][j], af[0], bf);
                mma_f16(acc[1][j], af[1], bf);
            }
        }
    }
    #pragma unroll
    for (int i = 0; i < 2; i++) {
        long row0 = bm + m0 + i * 16 + g;
        #pragma unroll
        for (int j = 0; j < 4; j++) {
            int col = bn + n0 + j * 8 + 2 * tg;
            #pragma unroll
            for (int half_ = 0; half_ < 2; half_++) {
                long row = row0 + half_ * 8;
                float v0 = acc[i][j][half_*2+0] * alpha;
                float v1 = acc[i][j][half_*2+1] * alpha;
                if (isq || col < 192) {
                    int h = col / 24, d = col - h * 24;
                    __half* dst = (isq ? qo + row * 256 : kvo + row * 512) + h * 32;
                    dst[hperm(d)]     = h16(v0);
                    dst[hperm(d + 1)] = h16(v1);
                    if (d < 8)     dst[18 + ((d >> 1) << 2) + (d & 1)]             = __float2half(0.f);
                    if (d + 1 < 8) dst[18 + (((d + 1) >> 1) << 2) + ((d + 1) & 1)] = __float2half(0.f);
                } else {
                    *(__half2*)&kvo[row * 512 + 256 + (col - 192)] = __floats2half2_rn(v0, v1);
                }
            }
        }
    }
}

// ================= conv3x3 implicit GEMM (fp16): 128x64, both streams ===========
__global__ __launch_bounds__(256, 3) void conv_f16k(
    const __half* __restrict__ nxg, const __half* __restrict__ nvg,
    const __half* __restrict__ Wq, const __half* __restrict__ Wv,
    const float* __restrict__ bq, const float* __restrict__ bv,
    __half* __restrict__ oq, __half* __restrict__ ov)
{
    extern __shared__ float sm_[];
    float* As = sm_;
    float* Bs = sm_ + ST * AWORDS;
    const int N = CC;
    int zsel = blockIdx.z;
    const __half* nhwc = zsel ? nvg : nxg;
    const __half* W    = zsel ? Wv  : Wq;
    const float* bias  = zsel ? bv  : bq;
    __half* C          = zsel ? ov  : oq;
    int tid = threadIdx.x;
    long bm = (long)blockIdx.y * 128;
    int bn = blockIdx.x * 64;
    int wid = tid >> 5, lane = tid & 31;
    int wm = wid >> 1, wn = wid & 1;
    int m0 = wm * 32, n0 = wn * 32;
    int g = lane >> 2, tg = lane & 3;

    int ar = tid >> 2, aseg = tid & 3;
    int asw = aseg ^ (ar & 3);

    uint32_t sAa = (uint32_t)__cvta_generic_to_shared(As);
    uint32_t sBa = (uint32_t)__cvta_generic_to_shared(Bs);
    uint32_t dA = sAa + (ar * 16 + asw * 4) * 4;
    uint32_t dB = sBa + (ar * 16 + asw * 4) * 4;
    const __half* pB = W + (long)(bn + ar) * KCONV + aseg * 8;
    const uint32_t stA = AWORDS * 4, stB = BWORDS * 4;
    const uint32_t rA = 64 * 16 * 4;

    int fo0 = (((tg >> 1) ^ (g & 3)) << 2) + ((tg & 1) << 1);
    int fo1 = fo0 ^ 8;

    const __half* base[2];
    int okb[2];
    #pragma unroll
    for (int h = 0; h < 2; h++) {
        long t = bm + ar + h * 64;
        int ix = t & 7, iy = (t >> 3) & 7, wx = (t >> 6) & 15, wy = (t >> 10) & 15;
        int b = (int)(t >> 14);
        int xs = wx * 8 + ix, ys = wy * 8 + iy;
        base[h] = nhwc + ((long)(b * HH + ys - 1) * WW + (xs - 1)) * CIN;
        int m = 0;
        #pragma unroll
        for (int ky = 0; ky < 3; ky++)
            #pragma unroll
            for (int kx = 0; kx < 3; kx++) {
                int sy = ys + ky - 1, sx = xs + kx - 1;
                if (sy >= 0 && sy < HH && sx >= 0 && sx < WW) m |= 1 << (ky * 3 + kx);
            }
        okb[h] = m;
    }

    float acc[2][4][4];
    #pragma unroll
    for (int i = 0; i < 2; i++)
        #pragma unroll
        for (int j = 0; j < 4; j++)
            #pragma unroll
            for (int r = 0; r < 4; r++) acc[i][j][r] = 0.f;

    const int NT = KCONV / 32;   // 27, 3 tiles per tap
    #pragma unroll
    for (int s = 0; s < ST - 1; s++) {
        int idx = s / 3, c0 = (s % 3) * 32;
        int ky = idx / 3, kx = idx % 3;
        long doff = ((long)ky * WW + kx) * CIN + c0 + aseg * 8;
        #pragma unroll
        for (int h = 0; h < 2; h++) {
            bool ok = (okb[h] >> idx) & 1;
            const void* src = ok ? (const void*)(base[h] + doff) : (const void*)W;
            cp16p(dA + s * stA + h * rA, src, ok ? 16 : 0);
        }
        cp16(dB + s * stB, pB + s * 32);
        CP_COMMIT();
    }
    for (int t = 0; t < NT; t++) {
        int buf = t % ST;
        CP_WAITN();
        __syncthreads();
        int tp = t + ST - 1;
        if (tp < NT) {
            int sb = tp % ST;
            int idx = tp / 3, c0 = (tp - idx * 3) * 32;
            int ky = idx / 3, kx = idx - ky * 3;
            long doff = ((long)ky * WW + kx) * CIN + c0 + aseg * 8;
            #pragma unroll
            for (int h = 0; h < 2; h++) {
                bool ok = (okb[h] >> idx) & 1;
                const void* src = ok ? (const void*)(base[h] + doff) : (const void*)W;
                cp16p(dA + sb * stA + h * rA, src, ok ? 16 : 0);
            }
            cp16(dB + sb * stB, pB + tp * 32);
        }
        CP_COMMIT();
        const float* as = As + buf * AWORDS;
        const float* bs = Bs + buf * BWORDS;
        #pragma unroll
        for (int s = 0; s < 2; s++) {
            int fo = s ? fo1 : fo0;
            uint32_t af[2][4];
            #pragma unroll
            for (int i = 0; i < 2; i++) {
                uint2 aLo = *(const uint2*)&as[(m0 + i*16 + g)     * 16 + fo];
                uint2 aHi = *(const uint2*)&as[(m0 + i*16 + g + 8) * 16 + fo];
                af[i][0] = aLo.x; af[i][1] = aHi.x; af[i][2] = aLo.y; af[i][3] = aHi.y;
            }
            #pragma unroll
            for (int j = 0; j < 4; j++) {
                uint2 bv = *(const uint2*)&bs[(n0 + j*8 + g) * 16 + fo];
                uint32_t bf[2] = { bv.x, bv.y };
                mma_f16(acc[0][j], af[0], bf);
                mma_f16(acc[1][j], af[1], bf);
            }
        }
    }
    #pragma unroll
    for (int i = 0; i < 2; i++) {
        long row0 = bm + m0 + i * 16 + g;
        #pragma unroll
        for (int j = 0; j < 4; j++) {
            int col = bn + n0 + j * 8 + 2 * tg;
            float b0 = bias[col], b1 = bias[col + 1];
            #pragma unroll
            for (int half_ = 0; half_ < 2; half_++) {
                long row = row0 + half_ * 8;
                *(__half2*)&C[row * N + col] =
                    __floats2half2_rn(acc[i][j][half_*2+0] + b0, acc[i][j][half_*2+1] + b1);
            }
        }
    }
}

// ---------------- windowed attention via tensor cores (R15, unchanged) ----------------
__global__ __launch_bounds__(256) void attn_mma(
    const __half* __restrict__ q, const __half* __restrict__ kv,
    const float* __restrict__ rpb, __half* __restrict__ out)
{
    extern __shared__ __align__(16) char smx[];
    __half* sh = (__half*)smx;
    float* s_rpb = (float*)(smx + AT_RPB_B);
    uint32_t sb = (uint32_t)__cvta_generic_to_shared(smx);
    int tid = threadIdx.x;
    long tb = (long)blockIdx.x * 64;

    for (int e = tid; e < 225 * 8; e += 256) s_rpb[e] = rpb[e];

    #pragma unroll
    for (int it = 0; it < 8; it++) {
        int idx = tid + it * 256;
        int r = idx >> 5, ch = idx & 31;
        int h = ch >> 2, aseg = ch & 3;
        uint32_t doff = (uint32_t)((h * 2048 + r * 32 + ((aseg ^ (r & 3)) << 3)) * 2);
        cp16(sb + doff,            q  + (tb + r) * 256 + ch * 8);
        cp16(sb + AT_K * 2 + doff, kv + (tb + r) * 512 + ch * 8);
    }
    #pragma unroll
    for (int it = 0; it < 6; it++) {
        int idx = tid + it * 256;
        int r = idx / 24, c = idx - r * 24;
        cp16(sb + (AT_VS + r * 200 + c * 8) * 2, kv + (tb + r) * 512 + 256 + c * 8);
    }
    CP_COMMIT();
    asm volatile("cp.async.wait_group 0;" ::: "memory");
    __syncthreads();

    #pragma unroll
    for (int it = 0; it < 48; it++) {
        int e = tid + it * 256;
        int t = e / 192, c = e - t * 192;
        __half val = sh[AT_VS + t * 200 + c];
        int h = c / 24, d = c - h * 24;
        int kp = hperm(t);
        int word = (kp >> 1) ^ ((d & 7) << 1);
        sh[AT_V + h * 2048 + d * 64 + word * 2 + (kp & 1)] = val;
    }
    __syncthreads();

    int wid = tid >> 5, lane = tid & 31;
    int g = lane >> 2, tg = lane & 3;
    int h = wid;
    const __half* Qh = sh + h * 2048;
    const __half* Kh = sh + AT_K + h * 2048;
    const __half* Vh = sh + AT_V + h * 2048;
    int fo0 = (((tg >> 1) ^ (g & 3)) << 2) + ((tg & 1) << 1);
    int fo1 = fo0 ^ 8;

    #pragma unroll
    for (int rb = 0; rb < 2; rb++) {
        float S[2][8][4];
        #pragma unroll
        for (int mi = 0; mi < 2; mi++)
            #pragma unroll
            for (int nj = 0; nj < 8; nj++)
                #pragma unroll
                for (int c = 0; c < 4; c++) S[mi][nj][c] = 0.f;

        #pragma unroll
        for (int kt = 0; kt < 2; kt++) {
            int fo = kt ? fo1 : fo0;
            uint32_t af[2][4];
            #pragma unroll
            for (int mi = 0; mi < 2; mi++) {
                int r0 = rb * 32 + mi * 16 + g;
                uint2 aLo = *(const uint2*)(Qh + r0 * 32 + fo * 2);
                uint2 aHi = *(const uint2*)(Qh + (r0 + 8) * 32 + fo * 2);
                af[mi][0] = aLo.x; af[mi][1] = aHi.x; af[mi][2] = aLo.y; af[mi][3] = aHi.y;
            }
            #pragma unroll
            for (int nj = 0; nj < 8; nj++) {
                int rr = nj * 8 + g;
                uint2 bv = *(const uint2*)(Kh + rr * 32 + fo * 2);
                uint32_t bf[2] = { bv.x, bv.y };
                mma_f16(S[0][nj], af[0], bf);
                mma_f16(S[1][nj], af[1], bf);
            }
        }
        float inv_[2][2];
        #pragma unroll
        for (int mi = 0; mi < 2; mi++)
            #pragma unroll
            for (int hs = 0; hs < 2; hs++) {
                int r = rb * 32 + mi * 16 + g + hs * 8;
                int iy = r >> 3, ix = r & 7;
                float mx = -1e30f;
                #pragma unroll
                for (int nj = 0; nj < 8; nj++) {
                    int c0 = nj * 8 + 2 * tg;
                    int bi = ((iy - (c0 >> 3) + 7) * 15 + (ix - (c0 & 7) + 7)) * 8 + h;
                    float v0 = S[mi][nj][hs*2]   + s_rpb[bi];
                    float v1 = S[mi][nj][hs*2+1] + s_rpb[bi - 8];
                    S[mi][nj][hs*2] = v0; S[mi][nj][hs*2+1] = v1;
                    mx = fmaxf(mx, fmaxf(v0, v1));
                }
                mx = fmaxf(mx, __shfl_xor_sync(~0u, mx, 1));
                mx = fmaxf(mx, __shfl_xor_sync(~0u, mx, 2));
                float sum = 0.f;
                #pragma unroll
                for (int nj = 0; nj < 8; nj++) {
                    float e0 = __expf(S[mi][nj][hs*2]   - mx);
                    float e1 = __expf(S[mi][nj][hs*2+1] - mx);
                    S[mi][nj][hs*2] = e0; S[mi][nj][hs*2+1] = e1;
                    sum += e0 + e1;
                }
                sum += __shfl_xor_sync(~0u, sum, 1);
                sum += __shfl_xor_sync(~0u, sum, 2);
                inv_[mi][hs] = 1.f / sum;
            }
        float O[2][3][4];
        #pragma unroll
        for (int mi = 0; mi < 2; mi++)
            #pragma unroll
            for (int nj = 0; nj < 3; nj++)
                #pragma unroll
                for (int c = 0; c < 4; c++) O[mi][nj][c] = 0.f;
        #pragma unroll
        for (int kt = 0; kt < 4; kt++) {
            uint32_t af[2][4];
            #pragma unroll
            for (int mi = 0; mi < 2; mi++) {
                af[mi][0] = h2u(S[mi][2*kt][0],   S[mi][2*kt][1]);
                af[mi][1] = h2u(S[mi][2*kt][2],   S[mi][2*kt][3]);
                af[mi][2] = h2u(S[mi][2*kt+1][0], S[mi][2*kt+1][1]);
                af[mi][3] = h2u(S[mi][2*kt+1][2], S[mi][2*kt+1][3]);
            }
            #pragma unroll
            for (int nj = 0; nj < 3; nj++) {
                int rr = nj * 8 + g;
                int word = (kt * 8 + 2 * tg) ^ ((rr & 7) << 1);
                uint2 bv = *(const uint2*)(Vh + rr * 64 + word * 2);
                uint32_t bf[2] = { bv.x, bv.y };
                mma_f16(O[0][nj], af[0], bf);
                mma_f16(O[1][nj], af[1], bf);
            }
        }
        #pragma unroll
        for (int mi = 0; mi < 2; mi++)
            #pragma unroll
            for (int nj = 0; nj < 3; nj++)
                #pragma unroll
                for (int c = 0; c < 4; c++) {
                    int hs = c >> 1;
                    int r = rb * 32 + mi * 16 + g + hs * 8;
                    float val = O[mi][nj][c] * inv_[mi][hs];
                    int dcol = h * 24 + nj * 8 + 2 * tg + (c & 1);
                    out[(tb + r) * 192 + hperm(dcol)] = h16(val);
                }
    }
}

// ---------------- row LN: half in (natural) -> half hperm out ----------------
__global__ __launch_bounds__(256) void ln_rows_h(
    const __half* __restrict__ in, const float* __restrict__ gamma,
    const float* __restrict__ beta, __half* __restrict__ out)
{
    int warp = threadIdx.x >> 5, lane = threadIdx.x & 31;
    long row = (long)blockIdx.x * 8 + warp;
    const __half* p = in + row * CC;
    float v[6];
    float sum = 0.f, sq = 0.f;
    #pragma unroll
    for (int k = 0; k < 6; k++) { v[k] = __half2float(p[lane + k * 32]); sum += v[k]; sq += v[k] * v[k]; }
    #pragma unroll
    for (int o = 16; o > 0; o >>= 1) { sum += __shfl_xor_sync(~0u, sum, o); sq += __shfl_xor_sync(~0u, sq, o); }
    float mean = sum * (1.f / CC), var = sq * (1.f / CC) - mean * mean;
    float rstd = rsqrtf(var + 1e-5f);
    __half* qo = out + row * CC;
    #pragma unroll
    for (int k = 0; k < 6; k++) {
        int c = lane + k * 32;
        qo[hperm(c)] = h16((v[k] - mean) * rstd * gamma[c] + beta[c]);
    }
}

// dual-tensor LN (LN1 + LN2), half in
__global__ __launch_bounds__(256) void ln_rows2_h(
    const __half* __restrict__ in1, const float* __restrict__ g1, const float* __restrict__ b1,
    __half* __restrict__ out1,
    const __half* __restrict__ in2, const float* __restrict__ g2, const float* __restrict__ b2,
    __half* __restrict__ out2)
{
    int warp = threadIdx.x >> 5, lane = threadIdx.x & 31;
    long gr = (long)blockIdx.x * 8 + warp;
    bool second = gr >= TT;
    long row = second ? gr - TT : gr;
    const __half* p = (second ? in2 : in1) + row * CC;
    const float* gamma = second ? g2 : g1;
    const float* beta  = second ? b2 : b1;
    __half* qo = (second ? out2 : out1) + row * CC;
    float v[6];
    float sum = 0.f, sq = 0.f;
    #pragma unroll
    for (int k = 0; k < 6; k++) { v[k] = __half2float(p[lane + k * 32]); sum += v[k]; sq += v[k] * v[k]; }
    #pragma unroll
    for (int o = 16; o > 0; o >>= 1) { sum += __shfl_xor_sync(~0u, sum, o); sq += __shfl_xor_sync(~0u, sq, o); }
    float mean = sum * (1.f / CC), var = sq * (1.f / CC) - mean * mean;
    float rstd = rsqrtf(var + 1e-5f);
    #pragma unroll
    for (int k = 0; k < 6; k++) {
        int c = lane + k * 32;
        qo[hperm(c)] = h16((v[k] - mean) * rstd * gamma[c] + beta[c]);
    }
}

// ---------------- LN4 + residual + window-reverse -> NCHW (fused, half inputs) ----------------
__global__ __launch_bounds__(256) void final_ln_kernel(
    const __half* __restrict__ m, const float* __restrict__ gamma, const float* __restrict__ beta,
    const __half* __restrict__ xp, const __half* __restrict__ vp, float* __restrict__ out)
{
    extern __shared__ float s[];   // 64 * 193
    int w = blockIdx.x;
    int b = w >> 8, wy = (w >> 4) & 15, wx = w & 15;
    long tb = (long)w * 64;
    int warp = threadIdx.x >> 5, lane = threadIdx.x & 31;
    #pragma unroll
    for (int tt = 0; tt < 8; tt++) {
        int tl = warp * 8 + tt;
        long row = (tb + tl) * CC;
        float v[6];
        float sum = 0.f, sq = 0.f;
        #pragma unroll
        for (int k = 0; k < 6; k++) { v[k] = __half2float(m[row + lane + k * 32]); sum += v[k]; sq += v[k] * v[k]; }
        #pragma unroll
        for (int o = 16; o > 0; o >>= 1) { sum += __shfl_xor_sync(~0u, sum, o); sq += __shfl_xor_sync(~0u, sq, o); }
        float mean = sum * (1.f / CC), var = sq * (1.f / CC) - mean * mean;
        float rstd = rsqrtf(var + 1e-5f);
        #pragma unroll
        for (int k = 0; k < 6; k++) {
            int c = lane + k * 32;
            s[tl * 193 + c] = (v[k] - mean) * rstd * gamma[c] + beta[c]
                              + __half2float(xp[row + c]) + __half2float(vp[row + c]);
        }
    }
    __syncthreads();
    long obase = (((long)(b * CC) * HH + wy * 8)) * WW + wx * 8;
    #pragma unroll
    for (int it = 0; it < 48; it++) {
        int e = threadIdx.x + it * 256;
        int c = e >> 6, p = e & 63;
        int iy = p >> 3, ix = p & 7;
        out[obase + (long)c * (HH * WW) + iy * WW + ix] = s[p * 193 + c];
    }
}

extern "C" void kernel_launch(void* const* d_in, const int* in_sizes, int n_in,
                              void* d_out, int out_size)
{
    const float* x    = (const float*)d_in[0];
    const float* v    = (const float*)d_in[1];
    const float* pq_w = (const float*)d_in[2];
    const float* pq_b = (const float*)d_in[3];
    const float* pv_w = (const float*)d_in[4];
    const float* pv_b = (const float*)d_in[5];
    const float* n1w  = (const float*)d_in[6];
    const float* n1b  = (const float*)d_in[7];
    const float* n2w  = (const float*)d_in[8];
    const float* n2b  = (const float*)d_in[9];
    const float* n3w  = (const float*)d_in[10];
    const float* n3b  = (const float*)d_in[11];
    const float* n4w  = (const float*)d_in[12];
    const float* n4b  = (const float*)d_in[13];
    const float* qw   = (const float*)d_in[14];
    const float* kvw  = (const float*)d_in[15];
    const float* apw  = (const float*)d_in[16];
    const float* apb  = (const float*)d_in[17];
    const float* rpb  = (const float*)d_in[18];
    const float* f1w  = (const float*)d_in[19];
    const float* f1b  = (const float*)d_in[20];
    const float* f2w  = (const float*)d_in[21];
    const float* f2b  = (const float*)d_in[22];
    float* out = (float*)d_out;
    (void)in_sizes; (void)n_in; (void)out_size;

    __half *nx,*nv,*xp,*vp,*xs,*vs,*q,*kv,*at,*pr,*l3,*h1,*m;
    __half *qwP,*kvwP,*apwP,*f1wP,*f2wP,*cqwP,*cvwP;
    cudaGetSymbolAddress((void**)&nx, g_nx);
    cudaGetSymbolAddress((void**)&nv, g_nv);
    cudaGetSymbolAddress((void**)&xp, g_xp);
    cudaGetSymbolAddress((void**)&vp, g_vp);
    cudaGetSymbolAddress((void**)&xs, g_xs);
    cudaGetSymbolAddress((void**)&vs, g_vs);
    cudaGetSymbolAddress((void**)&q , g_q );
    cudaGetSymbolAddress((void**)&kv, g_kv);
    cudaGetSymbolAddress((void**)&at, g_at);
    cudaGetSymbolAddress((void**)&pr, g_pr);
    cudaGetSymbolAddress((void**)&l3, g_l3);
    cudaGetSymbolAddress((void**)&h1, g_h1);
    cudaGetSymbolAddress((void**)&m , g_m );
    cudaGetSymbolAddress((void**)&qwP , g_qwP );
    cudaGetSymbolAddress((void**)&kvwP, g_kvwP);
    cudaGetSymbolAddress((void**)&apwP, g_apwP);
    cudaGetSymbolAddress((void**)&f1wP, g_f1wP);
    cudaGetSymbolAddress((void**)&f2wP, g_f2wP);
    cudaGetSymbolAddress((void**)&cqwP, g_cqwP);
    cudaGetSymbolAddress((void**)&cvwP, g_cvwP);

    const float SCALE = 0.20412414523193154f;  // 24^-0.5

    cudaFuncSetAttribute(mm_f16k<true,false,2>, cudaFuncAttributeMaxDynamicSharedMemorySize, SMEMB);
    cudaFuncSetAttribute(mm_f16k<true,true ,1>, cudaFuncAttributeMaxDynamicSharedMemorySize, SMEMB);
    cudaFuncSetAttribute(mm_qkv, cudaFuncAttributeMaxDynamicSharedMemorySize, SMEMB);
    cudaFuncSetAttribute(conv_f16k, cudaFuncAttributeMaxDynamicSharedMemorySize, SMEMB);
    cudaFuncSetAttribute(attn_mma, cudaFuncAttributeMaxDynamicSharedMemorySize, AT_SMEM);
    cudaFuncSetAttribute(final_ln_kernel, cudaFuncAttributeMaxDynamicSharedMemorySize, FLSMEM);

    long totalW = (long)S1 + S2 + S1 + S4 + S4 + S6 + S6;
    prep_weights<<<(int)((totalW + 255) / 256), 256>>>(
        qw, kvw, apw, f1w, f2w, pq_w, pv_w,
        qwP, kvwP, apwP, f1wP, f2wP, cqwP, cvwP);

    to_nhwc2<<<dim3(4,3,2048),dim3(32,8)>>>(x, v, nx, nv);

    conv_f16k<<<dim3(3,1024,2),256,SMEMB>>>(nx, nv, cqwP, cvwP, pq_b, pv_b, xp, vp);

    ln_rows2_h<<<32768,256>>>(xp, n1w, n1b, xs, vp, n2w, n2b, vs);

    mm_qkv<<<dim3(9,1024),256,SMEMB>>>(xs, vs, qwP, kvwP, q, kv, SCALE);

    attn_mma<<<2048,256,AT_SMEM>>>(q, kv, rpb, at);

    mm_f16k<true,false,2><<<dim3(3,1024),256,SMEMB>>>(at, apwP, apb, pr, TT, CC, CC, 1.f);

    ln_rows_h<<<16384,256>>>(pr, n3w, n3b, l3);

    mm_f16k<true,true ,1><<<dim3(12,1024),256,SMEMB>>>(l3, f1wP, f1b, h1, TT, FF, CC, 1.f);
    mm_f16k<true,false,2><<<dim3(3,1024),256,SMEMB>>>(h1, f2wP, f2b, m , TT, CC, FF, 2.f);

    final_ln_kernel<<<2048,256,FLSMEM>>>(m, n4w, n4b, xp, vp, out);
}

// round 17
// speedup vs baseline: 1.0502x; 1.0502x over previous
#include <cuda_runtime.h>
#include <cuda_fp16.h>
#include <math.h>
#include <stdint.h>

#define BB 8
#define CIN 96
#define CC 192
#define HH 128
#define WW 128
#define HEADS 8
#define HD 24
#define TT 131072
#define FF 768
#define KCONV 864   // 9*96

// pipeline: K-tile = 32 halves (64B/row)
#define ST 5
#define AWORDS (256*16)
#define BWORDS (64*16)
#define SMEMB (ST*(AWORDS+BWORDS)*4)
#define FLSMEM (64*193*4)

// attention smem (halves offsets) — no V staging; ~105.5KB -> 2 CTAs/SM
#define AT_Q  0
#define AT_K  16384
#define AT_V  32768
#define AT_RPB_B 98304
#define AT_SMEM (98304 + 7200)

// ---------------- scratch ----------------
__device__ __half g_nx[BB*CIN*HH*WW];
__device__ __half g_nv[BB*CIN*HH*WW];
__device__ __half g_xp[TT*CC];
__device__ __half g_vp[TT*CC];
__device__ __half g_xs[TT*CC];
__device__ __half g_vs[TT*CC];
__device__ __half g_q [(long)TT*256];    // [t][8 heads][32 padded hperm]
__device__ __half g_kv[(long)TT*512];    // [t][K: 8x32 padded hperm][V: 192 natural][64 pad]
__device__ __half g_at[TT*CC];
__device__ __half g_pr[TT*CC];
__device__ __half g_l3[TT*CC];
__device__ __half g_h1[(long)TT*FF];
__device__ __half g_m [TT*CC];
// weights: n-major, k-contiguous, k hperm'd, fp16
__device__ __half g_qwP [CC*CC];
__device__ __half g_kvwP[2*CC*CC];
__device__ __half g_apwP[CC*CC];
__device__ __half g_f1wP[FF*CC];
__device__ __half g_f2wP[CC*FF];
__device__ __half g_cqwP[CC*KCONV];
__device__ __half g_cvwP[CC*KCONV];

// ---------------- helpers ----------------
__device__ __forceinline__ int hperm(int k) {
    int r = k & 15;
    return (k & ~15) | (((r & 7) >> 1) << 2) | (((r >> 3) & 1) << 1) | (r & 1);
}
__device__ __forceinline__ __half h16(float x) { return __float2half_rn(x); }
__device__ __forceinline__ uint32_t h2u(float a, float b) {
    __half2 h = __floats2half2_rn(a, b);
    return *reinterpret_cast<uint32_t*>(&h);
}

__device__ __forceinline__ void mma_f16(float* d, const uint32_t* a, const uint32_t* b) {
    asm("mma.sync.aligned.m16n8k16.row.col.f32.f16.f16.f32 "
        "{%0,%1,%2,%3},{%4,%5,%6,%7},{%8,%9},{%10,%11,%12,%13};"
        : "=f"(d[0]), "=f"(d[1]), "=f"(d[2]), "=f"(d[3])
        : "r"(a[0]), "r"(a[1]), "r"(a[2]), "r"(a[3]),
          "r"(b[0]), "r"(b[1]),
          "f"(d[0]), "f"(d[1]), "f"(d[2]), "f"(d[3]));
}
__device__ __forceinline__ void cp16(uint32_t d, const void* s) {
    asm volatile("cp.async.cg.shared.global [%0], [%1], 16;" :: "r"(d), "l"(s));
}
__device__ __forceinline__ void cp16p(uint32_t d, const void* s, int sz) {
    asm volatile("cp.async.cg.shared.global [%0], [%1], 16, %2;" :: "r"(d), "l"(s), "r"(sz));
}
#define CP_COMMIT() asm volatile("cp.async.commit_group;")
#define CP_WAITN()  asm volatile("cp.async.wait_group 3;")

// ---------------- fused weight prep (fp16, hperm) ----------------
#define S1 (CC*CC)
#define S2 (2*CC*CC)
#define S4 (FF*CC)
#define S6 (KCONV*CC)
__global__ void prep_weights(
    const float* __restrict__ qw, const float* __restrict__ kvw, const float* __restrict__ apw,
    const float* __restrict__ f1w, const float* __restrict__ f2w,
    const float* __restrict__ cqw, const float* __restrict__ cvw,
    __half* __restrict__ qwP, __half* __restrict__ kvwP, __half* __restrict__ apwP,
    __half* __restrict__ f1wP, __half* __restrict__ f2wP,
    __half* __restrict__ cqwP, __half* __restrict__ cvwP)
{
    long i = (long)blockIdx.x * 256 + threadIdx.x;
    long o = i;
    if (o < S1) { int n=o/CC, k=o%CC; qwP[(long)n*CC + hperm(k)] = h16(qw[o]); return; }
    o -= S1;
    if (o < S2) { int n=o/CC, k=o%CC; kvwP[(long)n*CC + hperm(k)] = h16(kvw[o]); return; }
    o -= S2;
    if (o < S1) { int n=o/CC, k=o%CC; apwP[(long)n*CC + hperm(k)] = h16(apw[o]); return; }
    o -= S1;
    if (o < S4) { int n=o/CC, k=o%CC; f1wP[(long)n*CC + hperm(k)] = h16(f1w[o]); return; }
    o -= S4;
    if (o < S4) { int n=o/FF, k=o%FF; f2wP[(long)n*FF + hperm(k)] = h16(f2w[o]); return; }
    o -= S4;
    if (o < S6) { int oc=o/(CIN*9), rem=o%(CIN*9); int c=rem/9, kk=rem%9;
                  cqwP[(long)oc*KCONV + hperm(kk*CIN + c)] = h16(cqw[o]); return; }
    o -= S6;
    if (o < S6) { int oc=o/(CIN*9), rem=o%(CIN*9); int c=rem/9, kk=rem%9;
                  cvwP[(long)oc*KCONV + hperm(kk*CIN + c)] = h16(cvw[o]); return; }
}

// ---------------- NCHW -> NHWC (fp16, hperm on channel) ----------------
__global__ __launch_bounds__(256) void to_nhwc(const float* __restrict__ in, __half* __restrict__ out) {
    __shared__ float tile[32][33];
    int by = blockIdx.z; int b = by >> 7, y = by & 127;
    int c0 = blockIdx.y * 32, x0 = blockIdx.x * 32;
    int tx = threadIdx.x, ty = threadIdx.y;
    #pragma unroll
    for (int i = ty; i < 32; i += 8)
        tile[i][tx] = in[((long)(b * CIN + c0 + i) * HH + y) * WW + x0 + tx];
    __syncthreads();
    #pragma unroll
    for (int i = ty; i < 32; i += 8)
        out[((long)(b * HH + y) * WW + x0 + i) * CIN + hperm(c0 + tx)] = h16(tile[tx][i]);
}

// ================= fp16 MMA GEMM: block 256x64, warp 64x32, KT=32, 5 stages ======
// OUT: 1 = half hperm, 2 = half natural
template<bool BIAS, bool GELU, int OUT>
__global__ __launch_bounds__(256, 2) void mm_f16k(
    const __half* __restrict__ A, const __half* __restrict__ W,
    const float* __restrict__ bias, void* __restrict__ Cv,
    int M, int N, int K, float alpha)
{
    extern __shared__ float sm_[];
    float* As = sm_;
    float* Bs = sm_ + ST * AWORDS;
    int tid = threadIdx.x;
    long bm = (long)blockIdx.y * 256;
    int bn = blockIdx.x * 64;
    int wid = tid >> 5, lane = tid & 31;
    int wm = wid >> 1, wn = wid & 1;
    int m0 = wm * 64, n0 = wn * 32;
    int g = lane >> 2, tg = lane & 3;

    int ar = tid >> 2, aseg = tid & 3;
    int asw = aseg ^ (ar & 3);

    uint32_t sAa = (uint32_t)__cvta_generic_to_shared(As);
    uint32_t sBa = (uint32_t)__cvta_generic_to_shared(Bs);
    uint32_t dA = sAa + (ar * 16 + asw * 4) * 4;
    uint32_t dB = sBa + (ar * 16 + asw * 4) * 4;
    const __half* pA = A + (bm + ar) * K + aseg * 8;
    const __half* pB = W + (long)(bn + ar) * K + aseg * 8;
    const uint32_t stA = AWORDS * 4, stB = BWORDS * 4;
    const uint32_t rA = 64 * 16 * 4;
    const long     gA = (long)64 * K;

    int fo0 = (((tg >> 1) ^ (g & 3)) << 2) + ((tg & 1) << 1);
    int fo1 = fo0 ^ 8;

    float acc[4][4][4];
    #pragma unroll
    for (int i = 0; i < 4; i++)
        #pragma unroll
        for (int j = 0; j < 4; j++)
            #pragma unroll
            for (int r = 0; r < 4; r++) acc[i][j][r] = 0.f;

    int NT = K / 32;
    #pragma unroll
    for (int s = 0; s < ST - 1; s++) {
        if (s < NT) {
            #pragma unroll
            for (int h = 0; h < 4; h++) cp16(dA + s * stA + h * rA, pA + s * 32 + h * gA);
            cp16(dB + s * stB, pB + s * 32);
        }
        CP_COMMIT();
    }
    for (int t = 0; t < NT; t++) {
        int buf = t % ST;
        CP_WAITN();
        __syncthreads();
        int tp = t + ST - 1;
        if (tp < NT) {
            int sb = tp % ST;
            #pragma unroll
            for (int h = 0; h < 4; h++) cp16(dA + sb * stA + h * rA, pA + tp * 32 + h * gA);
            cp16(dB + sb * stB, pB + tp * 32);
        }
        CP_COMMIT();
        const float* as = As + buf * AWORDS;
        const float* bs = Bs + buf * BWORDS;
        #pragma unroll
        for (int s = 0; s < 2; s++) {
            int fo = s ? fo1 : fo0;
            uint32_t af[4][4];
            #pragma unroll
            for (int i = 0; i < 4; i++) {
                uint2 aLo = *(const uint2*)&as[(m0 + i*16 + g)     * 16 + fo];
                uint2 aHi = *(const uint2*)&as[(m0 + i*16 + g + 8) * 16 + fo];
                af[i][0] = aLo.x; af[i][1] = aHi.x; af[i][2] = aLo.y; af[i][3] = aHi.y;
            }
            #pragma unroll
            for (int j = 0; j < 4; j++) {
                uint2 bv = *(const uint2*)&bs[(n0 + j*8 + g) * 16 + fo];
                uint32_t bf[2] = { bv.x, bv.y };
                #pragma unroll
                for (int i = 0; i < 4; i++)
                    mma_f16(acc[i][j], af[i], bf);
            }
        }
    }
    __half* Ch = (__half*)Cv;
    #pragma unroll
    for (int i = 0; i < 4; i++) {
        long row0 = bm + m0 + i * 16 + g;
        #pragma unroll
        for (int j = 0; j < 4; j++) {
            int col = bn + n0 + j * 8 + 2 * tg;
            float b0 = 0.f, b1 = 0.f;
            if (BIAS) { b0 = bias[col]; b1 = bias[col + 1]; }
            #pragma unroll
            for (int half_ = 0; half_ < 2; half_++) {
                long row = row0 + half_ * 8;
                float v0 = (acc[i][j][half_ * 2 + 0] + b0) * alpha;
                float v1 = (acc[i][j][half_ * 2 + 1] + b1) * alpha;
                if (GELU) {
                    v0 = 0.5f * v0 * (1.f + erff(v0 * 0.70710678118654752f));
                    v1 = 0.5f * v1 * (1.f + erff(v1 * 0.70710678118654752f));
                }
                if (OUT == 1) {
                    Ch[row * N + hperm(col)]     = h16(v0);
                    Ch[row * N + hperm(col + 1)] = h16(v1);
                } else {
                    *(__half2*)&Ch[row * N + col] = __floats2half2_rn(v0, v1);
                }
            }
        }
    }
}

// ================= q + kv projections (grid.x = 9), padded half output ==========
__global__ __launch_bounds__(256, 2) void mm_qkv(
    const __half* __restrict__ xs, const __half* __restrict__ vs,
    const __half* __restrict__ qwP, const __half* __restrict__ kvwP,
    __half* __restrict__ qo, __half* __restrict__ kvo, float scaleq)
{
    extern __shared__ float sm_[];
    float* As = sm_;
    float* Bs = sm_ + ST * AWORDS;
    const int K = CC;
    int bx = blockIdx.x;
    bool isq = bx < 3;
    const __half* A = isq ? xs : vs;
    const __half* W = isq ? qwP : kvwP;
    int bn = (isq ? bx : bx - 3) * 64;
    float alpha = isq ? scaleq : 1.f;

    int tid = threadIdx.x;
    long bm = (long)blockIdx.y * 256;
    int wid = tid >> 5, lane = tid & 31;
    int wm = wid >> 1, wn = wid & 1;
    int m0 = wm * 64, n0 = wn * 32;
    int g = lane >> 2, tg = lane & 3;

    int ar = tid >> 2, aseg = tid & 3;
    int asw = aseg ^ (ar & 3);

    uint32_t sAa = (uint32_t)__cvta_generic_to_shared(As);
    uint32_t sBa = (uint32_t)__cvta_generic_to_shared(Bs);
    uint32_t dA = sAa + (ar * 16 + asw * 4) * 4;
    uint32_t dB = sBa + (ar * 16 + asw * 4) * 4;
    const __half* pA = A + (bm + ar) * K + aseg * 8;
    const __half* pB = W + (long)(bn + ar) * K + aseg * 8;
    const uint32_t stA = AWORDS * 4, stB = BWORDS * 4;
    const uint32_t rA = 64 * 16 * 4;
    const long     gA = (long)64 * K;

    int fo0 = (((tg >> 1) ^ (g & 3)) << 2) + ((tg & 1) << 1);
    int fo1 = fo0 ^ 8;

    float acc[4][4][4];
    #pragma unroll
    for (int i = 0; i < 4; i++)
        #pragma unroll
        for (int j = 0; j < 4; j++)
            #pragma unroll
            for (int r = 0; r < 4; r++) acc[i][j][r] = 0.f;

    const int NT = K / 32;   // 6
    #pragma unroll
    for (int s = 0; s < ST - 1; s++) {
        #pragma unroll
        for (int h = 0; h < 4; h++) cp16(dA + s * stA + h * rA, pA + s * 32 + h * gA);
        cp16(dB + s * stB, pB + s * 32);
        CP_COMMIT();
    }
    for (int t = 0; t < NT; t++) {
        int buf = t % ST;
        CP_WAITN();
        __syncthreads();
        int tp = t + ST - 1;
        if (tp < NT) {
            int sb = tp % ST;
            #pragma unroll
            for (int h = 0; h < 4; h++) cp16(dA + sb * stA + h * rA, pA + tp * 32 + h * gA);
            cp16(dB + sb * stB, pB + tp * 32);
        }
        CP_COMMIT();
        const float* as = As + buf * AWORDS;
        const float* bs = Bs + buf * BWORDS;
        #pragma unroll
        for (int s = 0; s < 2; s++) {
            int fo = s ? fo1 : fo0;
            uint32_t af[4][4];
            #pragma unroll
            for (int i = 0; i < 4; i++) {
                uint2 aLo = *(const uint2*)&as[(m0 + i*16 + g)     * 16 + fo];
                uint2 aHi = *(const uint2*)&as[(m0 + i*16 + g + 8) * 16 + fo];
                af[i][0] = aLo.x; af[i][1] = aHi.x; af[i][2] = aLo.y; af[i][3] = aHi.y;
            }
            #pragma unroll
            for (int j = 0; j < 4; j++) {
                uint2 bv = *(const uint2*)&bs[(n0 + j*8 + g) * 16 + fo];
                uint32_t bf[2] = { bv.x, bv.y };
                #pragma unroll
                for (int i = 0; i < 4; i++)
                    mma_f16(acc[i][j], af[i], bf);
            }
        }
    }
    #pragma unroll
    for (int i = 0; i < 4; i++) {
        long row0 = bm + m0 + i * 16 + g;
        #pragma unroll
        for (int j = 0; j < 4; j++) {
            int col = bn + n0 + j * 8 + 2 * tg;
            #pragma unroll
            for (int half_ = 0; half_ < 2; half_++) {
                long row = row0 + half_ * 8;
                float v0 = acc[i][j][half_*2+0] * alpha;
                float v1 = acc[i][j][half_*2+1] * alpha;
                if (isq || col < 192) {
                    int h = col / 24, d = col - h * 24;
                    __half* dst = (isq ? qo + row * 256 : kvo + row * 512) + h * 32;
                    dst[hperm(d)]     = h16(v0);
                    dst[hperm(d + 1)] = h16(v1);
                    if (d < 8)     dst[18 + ((d >> 1) << 2) + (d & 1)]             = __float2half(0.f);
                    if (d + 1 < 8) dst[18 + (((d + 1) >> 1) << 2) + ((d + 1) & 1)] = __float2half(0.f);
                } else {
                    *(__half2*)&kvo[row * 512 + 256 + (col - 192)] = __floats2half2_rn(v0, v1);
                }
            }
        }
    }
}

// ================= conv3x3 implicit GEMM (fp16): 256x64, KT=32, half out =========
__global__ __launch_bounds__(256, 2) void conv_f16k(
    const __half* __restrict__ nhwc, const __half* __restrict__ W,
    const float* __restrict__ bias, __half* __restrict__ C)
{
    extern __shared__ float sm_[];
    float* As = sm_;
    float* Bs = sm_ + ST * AWORDS;
    const int N = CC;
    int tid = threadIdx.x;
    long bm = (long)blockIdx.y * 256;
    int bn = blockIdx.x * 64;
    int wid = tid >> 5, lane = tid & 31;
    int wm = wid >> 1, wn = wid & 1;
    int m0 = wm * 64, n0 = wn * 32;
    int g = lane >> 2, tg = lane & 3;

    int ar = tid >> 2, aseg = tid & 3;
    int asw = aseg ^ (ar & 3);

    uint32_t sAa = (uint32_t)__cvta_generic_to_shared(As);
    uint32_t sBa = (uint32_t)__cvta_generic_to_shared(Bs);
    uint32_t dA = sAa + (ar * 16 + asw * 4) * 4;
    uint32_t dB = sBa + (ar * 16 + asw * 4) * 4;
    const __half* pB = W + (long)(bn + ar) * KCONV + aseg * 8;
    const uint32_t stA = AWORDS * 4, stB = BWORDS * 4;
    const uint32_t rA = 64 * 16 * 4;

    int fo0 = (((tg >> 1) ^ (g & 3)) << 2) + ((tg & 1) << 1);
    int fo1 = fo0 ^ 8;

    const __half* base[4];
    int okb[4];
    #pragma unroll
    for (int h = 0; h < 4; h++) {
        long t = bm + ar + h * 64;
        int ix = t & 7, iy = (t >> 3) & 7, wx = (t >> 6) & 15, wy = (t >> 10) & 15;
        int b = (int)(t >> 14);
        int xs = wx * 8 + ix, ys = wy * 8 + iy;
        base[h] = nhwc + ((long)(b * HH + ys - 1) * WW + (xs - 1)) * CIN;
        int m = 0;
        #pragma unroll
        for (int ky = 0; ky < 3; ky++)
            #pragma unroll
            for (int kx = 0; kx < 3; kx++) {
                int sy = ys + ky - 1, sx = xs + kx - 1;
                if (sy >= 0 && sy < HH && sx >= 0 && sx < WW) m |= 1 << (ky * 3 + kx);
            }
        okb[h] = m;
    }

    float acc[4][4][4];
    #pragma unroll
    for (int i = 0; i < 4; i++)
        #pragma unroll
        for (int j = 0; j < 4; j++)
            #pragma unroll
            for (int r = 0; r < 4; r++) acc[i][j][r] = 0.f;

    const int NT = KCONV / 32;   // 27, 3 tiles per tap
    #pragma unroll
    for (int s = 0; s < ST - 1; s++) {
        int idx = s / 3, c0 = (s % 3) * 32;
        int ky = idx / 3, kx = idx % 3;
        long doff = ((long)ky * WW + kx) * CIN + c0 + aseg * 8;
        #pragma unroll
        for (int h = 0; h < 4; h++) {
            bool ok = (okb[h] >> idx) & 1;
            const void* src = ok ? (const void*)(base[h] + doff) : (const void*)W;
            cp16p(dA + s * stA + h * rA, src, ok ? 16 : 0);
        }
        cp16(dB + s * stB, pB + s * 32);
        CP_COMMIT();
    }
    for (int t = 0; t < NT; t++) {
        int buf = t % ST;
        CP_WAITN();
        __syncthreads();
        int tp = t + ST - 1;
        if (tp < NT) {
            int sb = tp % ST;
            int idx = tp / 3, c0 = (tp - idx * 3) * 32;
            int ky = idx / 3, kx = idx - ky * 3;
            long doff = ((long)ky * WW + kx) * CIN + c0 + aseg * 8;
            #pragma unroll
            for (int h = 0; h < 4; h++) {
                bool ok = (okb[h] >> idx) & 1;
                const void* src = ok ? (const void*)(base[h] + doff) : (const void*)W;
                cp16p(dA + sb * stA + h * rA, src, ok ? 16 : 0);
            }
            cp16(dB + sb * stB, pB + tp * 32);
        }
        CP_COMMIT();
        const float* as = As + buf * AWORDS;
        const float* bs = Bs + buf * BWORDS;
        #pragma unroll
        for (int s = 0; s < 2; s++) {
            int fo = s ? fo1 : fo0;
            uint32_t af[4][4];
            #pragma unroll
            for (int i = 0; i < 4; i++) {
                uint2 aLo = *(const uint2*)&as[(m0 + i*16 + g)     * 16 + fo];
                uint2 aHi = *(const uint2*)&as[(m0 + i*16 + g + 8) * 16 + fo];
                af[i][0] = aLo.x; af[i][1] = aHi.x; af[i][2] = aLo.y; af[i][3] = aHi.y;
            }
            #pragma unroll
            for (int j = 0; j < 4; j++) {
                uint2 bv = *(const uint2*)&bs[(n0 + j*8 + g) * 16 + fo];
                uint32_t bf[2] = { bv.x, bv.y };
                #pragma unroll
                for (int i = 0; i < 4; i++)
                    mma_f16(acc[i][j], af[i], bf);
            }
        }
    }
    #pragma unroll
    for (int i = 0; i < 4; i++) {
        long row0 = bm + m0 + i * 16 + g;
        #pragma unroll
        for (int j = 0; j < 4; j++) {
            int col = bn + n0 + j * 8 + 2 * tg;
            float b0 = bias[col], b1 = bias[col + 1];
            #pragma unroll
            for (int half_ = 0; half_ < 2; half_++) {
                long row = row0 + half_ * 8;
                *(__half2*)&C[row * N + col] =
                    __floats2half2_rn(acc[i][j][half_*2+0] + b0, acc[i][j][half_*2+1] + b1);
            }
        }
    }
}

// ---------------- windowed attention via tensor cores (2 CTAs/SM) ----------------
__global__ __launch_bounds__(256) void attn_mma(
    const __half* __restrict__ q, const __half* __restrict__ kv,
    const float* __restrict__ rpb, __half* __restrict__ out)
{
    extern __shared__ __align__(16) char smx[];
    __half* sh = (__half*)smx;
    float* s_rpb = (float*)(smx + AT_RPB_B);
    uint32_t sb = (uint32_t)__cvta_generic_to_shared(smx);
    int tid = threadIdx.x;
    long tb = (long)blockIdx.x * 64;

    for (int e = tid; e < 225 * 8; e += 256) s_rpb[e] = rpb[e];

    // Q + K tile loads (straight swizzled copies)
    #pragma unroll
    for (int it = 0; it < 8; it++) {
        int idx = tid + it * 256;
        int r = idx >> 5, ch = idx & 31;
        int h = ch >> 2, aseg = ch & 3;
        uint32_t doff = (uint32_t)((h * 2048 + r * 32 + ((aseg ^ (r & 3)) << 3)) * 2);
        cp16(sb + doff,            q  + (tb + r) * 256 + ch * 8);
        cp16(sb + AT_K * 2 + doff, kv + (tb + r) * 512 + ch * 8);
    }
    CP_COMMIT();

    // V: direct global->register->smem transpose (L2-resident; no staging buffer)
    #pragma unroll
    for (int it = 0; it < 48; it++) {
        int e = tid + it * 256;                 // 0..12287, contiguous over t*192+c
        int t = e / 192, c = e - t * 192;
        __half val = kv[(tb + t) * 512 + 256 + c];
        int h = c / 24, d = c - h * 24;
        int kp = hperm(t);
        int word = (kp >> 1) ^ ((d & 7) << 1);
        sh[AT_V + h * 2048 + d * 64 + word * 2 + (kp & 1)] = val;
    }
    asm volatile("cp.async.wait_group 0;" ::: "memory");
    __syncthreads();

    int wid = tid >> 5, lane = tid & 31;
    int g = lane >> 2, tg = lane & 3;
    int h = wid;
    const __half* Qh = sh + h * 2048;
    const __half* Kh = sh + AT_K + h * 2048;
    const __half* Vh = sh + AT_V + h * 2048;
    int fo0 = (((tg >> 1) ^ (g & 3)) << 2) + ((tg & 1) << 1);
    int fo1 = fo0 ^ 8;

    #pragma unroll
    for (int rb = 0; rb < 2; rb++) {
        float S[2][8][4];
        #pragma unroll
        for (int mi = 0; mi < 2; mi++)
            #pragma unroll
            for (int nj = 0; nj < 8; nj++)
                #pragma unroll
                for (int c = 0; c < 4; c++) S[mi][nj][c] = 0.f;

        #pragma unroll
        for (int kt = 0; kt < 2; kt++) {
            int fo = kt ? fo1 : fo0;
            uint32_t af[2][4];
            #pragma unroll
            for (int mi = 0; mi < 2; mi++) {
                int r0 = rb * 32 + mi * 16 + g;
                uint2 aLo = *(const uint2*)(Qh + r0 * 32 + fo * 2);
                uint2 aHi = *(const uint2*)(Qh + (r0 + 8) * 32 + fo * 2);
                af[mi][0] = aLo.x; af[mi][1] = aHi.x; af[mi][2] = aLo.y; af[mi][3] = aHi.y;
            }
            #pragma unroll
            for (int nj = 0; nj < 8; nj++) {
                int rr = nj * 8 + g;
                uint2 bv = *(const uint2*)(Kh + rr * 32 + fo * 2);
                uint32_t bf[2] = { bv.x, bv.y };
                mma_f16(S[0][nj], af[0], bf);
                mma_f16(S[1][nj], af[1], bf);
            }
        }
        float inv_[2][2];
        #pragma unroll
        for (int mi = 0; mi < 2; mi++)
            #pragma unroll
            for (int hs = 0; hs < 2; hs++) {
                int r = rb * 32 + mi * 16 + g + hs * 8;
                int iy = r >> 3, ix = r & 7;
                float mx = -1e30f;
                #pragma unroll
                for (int nj = 0; nj < 8; nj++) {
                    int c0 = nj * 8 + 2 * tg;
                    int bi = ((iy - (c0 >> 3) + 7) * 15 + (ix - (c0 & 7) + 7)) * 8 + h;
                    float v0 = S[mi][nj][hs*2]   + s_rpb[bi];
                    float v1 = S[mi][nj][hs*2+1] + s_rpb[bi - 8];
                    S[mi][nj][hs*2] = v0; S[mi][nj][hs*2+1] = v1;
                    mx = fmaxf(mx, fmaxf(v0, v1));
                }
                mx = fmaxf(mx, __shfl_xor_sync(~0u, mx, 1));
                mx = fmaxf(mx, __shfl_xor_sync(~0u, mx, 2));
                float sum = 0.f;
                #pragma unroll
                for (int nj = 0; nj < 8; nj++) {
                    float e0 = __expf(S[mi][nj][hs*2]   - mx);
                    float e1 = __expf(S[mi][nj][hs*2+1] - mx);
                    S[mi][nj][hs*2] = e0; S[mi][nj][hs*2+1] = e1;
                    sum += e0 + e1;
                }
                sum += __shfl_xor_sync(~0u, sum, 1);
                sum += __shfl_xor_sync(~0u, sum, 2);
                inv_[mi][hs] = 1.f / sum;
            }
        float O[2][3][4];
        #pragma unroll
        for (int mi = 0; mi < 2; mi++)
            #pragma unroll
            for (int nj = 0; nj < 3; nj++)
                #pragma unroll
                for (int c = 0; c < 4; c++) O[mi][nj][c] = 0.f;
        #pragma unroll
        for (int kt = 0; kt < 4; kt++) {
            uint32_t af[2][4];
            #pragma unroll
            for (int mi = 0; mi < 2; mi++) {
                af[mi][0] = h2u(S[mi][2*kt][0],   S[mi][2*kt][1]);
                af[mi][1] = h2u(S[mi][2*kt][2],   S[mi][2*kt][3]);
                af[mi][2] = h2u(S[mi][2*kt+1][0], S[mi][2*kt+1][1]);
                af[mi][3] = h2u(S[mi][2*kt+1][2], S[mi][2*kt+1][3]);
            }
            #pragma unroll
            for (int nj = 0; nj < 3; nj++) {
                int rr = nj * 8 + g;
                int word = (kt * 8 + 2 * tg) ^ ((rr & 7) << 1);
                uint2 bv = *(const uint2*)(Vh + rr * 64 + word * 2);
                uint32_t bf[2] = { bv.x, bv.y };
                mma_f16(O[0][nj], af[0], bf);
                mma_f16(O[1][nj], af[1], bf);
            }
        }
        #pragma unroll
        for (int mi = 0; mi < 2; mi++)
            #pragma unroll
            for (int nj = 0; nj < 3; nj++)
                #pragma unroll
                for (int c = 0; c < 4; c++) {
                    int hs = c >> 1;
                    int r = rb * 32 + mi * 16 + g + hs * 8;
                    float val = O[mi][nj][c] * inv_[mi][hs];
                    int dcol = h * 24 + nj * 8 + 2 * tg + (c & 1);
                    out[(tb + r) * 192 + hperm(dcol)] = h16(val);
                }
    }
}

// ---------------- row LN: half in (natural) -> half hperm out ----------------
__global__ __launch_bounds__(256) void ln_rows_h(
    const __half* __restrict__ in, const float* __restrict__ gamma,
    const float* __restrict__ beta, __half* __restrict__ out)
{
    int warp = threadIdx.x >> 5, lane = threadIdx.x & 31;
    long row = (long)blockIdx.x * 8 + warp;
    const __half* p = in + row * CC;
    float v[6];
    float sum = 0.f, sq = 0.f;
    #pragma unroll
    for (int k = 0; k < 6; k++) { v[k] = __half2float(p[lane + k * 32]); sum += v[k]; sq += v[k] * v[k]; }
    #pragma unroll
    for (int o = 16; o > 0; o >>= 1) { sum += __shfl_xor_sync(~0u, sum, o); sq += __shfl_xor_sync(~0u, sq, o); }
    float mean = sum * (1.f / CC), var = sq * (1.f / CC) - mean * mean;
    float rstd = rsqrtf(var + 1e-5f);
    __half* qo = out + row * CC;
    #pragma unroll
    for (int k = 0; k < 6; k++) {
        int c = lane + k * 32;
        qo[hperm(c)] = h16((v[k] - mean) * rstd * gamma[c] + beta[c]);
    }
}

// dual-tensor LN (LN1 + LN2), half in
__global__ __launch_bounds__(256) void ln_rows2_h(
    const __half* __restrict__ in1, const float* __restrict__ g1, const float* __restrict__ b1,
    __half* __restrict__ out1,
    const __half* __restrict__ in2, const float* __restrict__ g2, const float* __restrict__ b2,
    __half* __restrict__ out2)
{
    int warp = threadIdx.x >> 5, lane = threadIdx.x & 31;
    long gr = (long)blockIdx.x * 8 + warp;
    bool second = gr >= TT;
    long row = second ? gr - TT : gr;
    const __half* p = (second ? in2 : in1) + row * CC;
    const float* gamma = second ? g2 : g1;
    const float* beta  = second ? b2 : b1;
    __half* qo = (second ? out2 : out1) + row * CC;
    float v[6];
    float sum = 0.f, sq = 0.f;
    #pragma unroll
    for (int k = 0; k < 6; k++) { v[k] = __half2float(p[lane + k * 32]); sum += v[k]; sq += v[k] * v[k]; }
    #pragma unroll
    for (int o = 16; o > 0; o >>= 1) { sum += __shfl_xor_sync(~0u, sum, o); sq += __shfl_xor_sync(~0u, sq, o); }
    float mean = sum * (1.f / CC), var = sq * (1.f / CC) - mean * mean;
    float rstd = rsqrtf(var + 1e-5f);
    #pragma unroll
    for (int k = 0; k < 6; k++) {
        int c = lane + k * 32;
        qo[hperm(c)] = h16((v[k] - mean) * rstd * gamma[c] + beta[c]);
    }
}

// ---------------- LN4 + residual + window-reverse -> NCHW (fused, half inputs) ----------------
__global__ __launch_bounds__(256) void final_ln_kernel(
    const __half* __restrict__ m, const float* __restrict__ gamma, const float* __restrict__ beta,
    const __half* __restrict__ xp, const __half* __restrict__ vp, float* __restrict__ out)
{
    extern __shared__ float s[];   // 64 * 193
    int w = blockIdx.x;
    int b = w >> 8, wy = (w >> 4) & 15, wx = w & 15;
    long tb = (long)w * 64;
    int warp = threadIdx.x >> 5, lane = threadIdx.x & 31;
    #pragma unroll
    for (int tt = 0; tt < 8; tt++) {
        int tl = warp * 8 + tt;
        long row = (tb + tl) * CC;
        float v[6];
        float sum = 0.f, sq = 0.f;
        #pragma unroll
        for (int k = 0; k < 6; k++) { v[k] = __half2float(m[row + lane + k * 32]); sum += v[k]; sq += v[k] * v[k]; }
        #pragma unroll
        for (int o = 16; o > 0; o >>= 1) { sum += __shfl_xor_sync(~0u, sum, o); sq += __shfl_xor_sync(~0u, sq, o); }
        float mean = sum * (1.f / CC), var = sq * (1.f / CC) - mean * mean;
        float rstd = rsqrtf(var + 1e-5f);
        #pragma unroll
        for (int k = 0; k < 6; k++) {
            int c = lane + k * 32;
            s[tl * 193 + c] = (v[k] - mean) * rstd * gamma[c] + beta[c]
                              + __half2float(xp[row + c]) + __half2float(vp[row + c]);
        }
    }
    __syncthreads();
    long obase = (((long)(b * CC) * HH + wy * 8)) * WW + wx * 8;
    #pragma unroll
    for (int it = 0; it < 48; it++) {
        int e = threadIdx.x + it * 256;
        int c = e >> 6, p = e & 63;
        int iy = p >> 3, ix = p & 7;
        out[obase + (long)c * (HH * WW) + iy * WW + ix] = s[p * 193 + c];
    }
}

extern "C" void kernel_launch(void* const* d_in, const int* in_sizes, int n_in,
                              void* d_out, int out_size)
{
    const float* x    = (const float*)d_in[0];
    const float* v    = (const float*)d_in[1];
    const float* pq_w = (const float*)d_in[2];
    const float* pq_b = (const float*)d_in[3];
    const float* pv_w = (const float*)d_in[4];
    const float* pv_b = (const float*)d_in[5];
    const float* n1w  = (const float*)d_in[6];
    const float* n1b  = (const float*)d_in[7];
    const float* n2w  = (const float*)d_in[8];
    const float* n2b  = (const float*)d_in[9];
    const float* n3w  = (const float*)d_in[10];
    const float* n3b  = (const float*)d_in[11];
    const float* n4w  = (const float*)d_in[12];
    const float* n4b  = (const float*)d_in[13];
    const float* qw   = (const float*)d_in[14];
    const float* kvw  = (const float*)d_in[15];
    const float* apw  = (const float*)d_in[16];
    const float* apb  = (const float*)d_in[17];
    const float* rpb  = (const float*)d_in[18];
    const float* f1w  = (const float*)d_in[19];
    const float* f1b  = (const float*)d_in[20];
    const float* f2w  = (const float*)d_in[21];
    const float* f2b  = (const float*)d_in[22];
    float* out = (float*)d_out;
    (void)in_sizes; (void)n_in; (void)out_size;

    __half *nx,*nv,*xp,*vp,*xs,*vs,*q,*kv,*at,*pr,*l3,*h1,*m;
    __half *qwP,*kvwP,*apwP,*f1wP,*f2wP,*cqwP,*cvwP;
    cudaGetSymbolAddress((void**)&nx, g_nx);
    cudaGetSymbolAddress((void**)&nv, g_nv);
    cudaGetSymbolAddress((void**)&xp, g_xp);
    cudaGetSymbolAddress((void**)&vp, g_vp);
    cudaGetSymbolAddress((void**)&xs, g_xs);
    cudaGetSymbolAddress((void**)&vs, g_vs);
    cudaGetSymbolAddress((void**)&q , g_q );
    cudaGetSymbolAddress((void**)&kv, g_kv);
    cudaGetSymbolAddress((void**)&at, g_at);
    cudaGetSymbolAddress((void**)&pr, g_pr);
    cudaGetSymbolAddress((void**)&l3, g_l3);
    cudaGetSymbolAddress((void**)&h1, g_h1);
    cudaGetSymbolAddress((void**)&m , g_m );
    cudaGetSymbolAddress((void**)&qwP , g_qwP );
    cudaGetSymbolAddress((void**)&kvwP, g_kvwP);
    cudaGetSymbolAddress((void**)&apwP, g_apwP);
    cudaGetSymbolAddress((void**)&f1wP, g_f1wP);
    cudaGetSymbolAddress((void**)&f2wP, g_f2wP);
    cudaGetSymbolAddress((void**)&cqwP, g_cqwP);
    cudaGetSymbolAddress((void**)&cvwP, g_cvwP);

    const float SCALE = 0.20412414523193154f;  // 24^-0.5

    cudaFuncSetAttribute(mm_f16k<true,false,2>, cudaFuncAttributeMaxDynamicSharedMemorySize, SMEMB);
    cudaFuncSetAttribute(mm_f16k<true,true ,1>, cudaFuncAttributeMaxDynamicSharedMemorySize, SMEMB);
    cudaFuncSetAttribute(mm_qkv, cudaFuncAttributeMaxDynamicSharedMemorySize, SMEMB);
    cudaFuncSetAttribute(conv_f16k, cudaFuncAttributeMaxDynamicSharedMemorySize, SMEMB);
    cudaFuncSetAttribute(attn_mma, cudaFuncAttributeMaxDynamicSharedMemorySize, AT_SMEM);
    cudaFuncSetAttribute(final_ln_kernel, cudaFuncAttributeMaxDynamicSharedMemorySize, FLSMEM);

    long totalW = (long)S1 + S2 + S1 + S4 + S4 + S6 + S6;
    prep_weights<<<(int)((totalW + 255) / 256), 256>>>(
        qw, kvw, apw, f1w, f2w, pq_w, pv_w,
        qwP, kvwP, apwP, f1wP, f2wP, cqwP, cvwP);

    to_nhwc<<<dim3(4,3,1024),dim3(32,8)>>>(x, nx);
    to_nhwc<<<dim3(4,3,1024),dim3(32,8)>>>(v, nv);

    conv_f16k<<<dim3(3,512),256,SMEMB>>>(nx, cqwP, pq_b, xp);
    conv_f16k<<<dim3(3,512),256,SMEMB>>>(nv, cvwP, pv_b, vp);

    ln_rows2_h<<<32768,256>>>(xp, n1w, n1b, xs, vp, n2w, n2b, vs);

    mm_qkv<<<dim3(9,512),256,SMEMB>>>(xs, vs, qwP, kvwP, q, kv, SCALE);

    attn_mma<<<2048,256,AT_SMEM>>>(q, kv, rpb, at);

    mm_f16k<true,false,2><<<dim3(3,512),256,SMEMB>>>(at, apwP, apb, pr, TT, CC, CC, 1.f);

    ln_rows_h<<<16384,256>>>(pr, n3w, n3b, l3);

    mm_f16k<true,true ,1><<<dim3(12,512),256,SMEMB>>>(l3, f1wP, f1b, h1, TT, FF, CC, 1.f);
    mm_f16k<true,false,2><<<dim3(3,512),256,SMEMB>>>(h1, f2wP, f2b, m , TT, CC, FF, 2.f);

    final_ln_kernel<<<2048,256,FLSMEM>>>(m, n4w, n4b, xp, vp, out);
}